// round 4
// baseline (speedup 1.0000x reference)
#include <cuda_runtime.h>
#include <math.h>

// ---------------- problem constants ----------------
#define BB    64
#define NIN   1024
#define NHID  1024
#define NOUT  10
#define TSN   500          // time bins
#define KS    77           // SRM kernel taps (truncated alpha kernel, tau=10)
#define KR    11           // refractory kernel taps (tau=1), REF[0]==0
#define THETA 10.0f
#define TT    25           // timesteps per spmm block (mask fits in u32)
#define NTG   (TSN / TT)   // 20

// ---------------- scratch (static device memory; no allocations) ----------------
__device__ float g_srm[KS];
__device__ float g_refk[KR];
__device__ float g_w1t[(size_t)NIN * NHID];          // 4 MB, W1 transposed [i][o]
__device__ float g_z1[(size_t)BB * NHID * TSN];      // 131 MB (z, then u in-place)
__device__ float g_s1[(size_t)BB * NHID * TSN];      // 131 MB
__device__ float g_z2[(size_t)BB * NOUT * TSN];      // 1.28 MB
__device__ float g_u2[(size_t)BB * NOUT * TSN];      // 1.28 MB

// ---------------- kernel tap init (double, matches python math.exp -> f32) ----------------
__global__ void init_kernel() {
    int i = threadIdx.x;
    if (i < KS) {
        double t = (double)i;
        g_srm[i] = (float)(t / 10.0 * exp(1.0 - t / 10.0));
    }
    if (i < KR) {
        double t = (double)i;
        g_refk[i] = (float)(-20.0 * t * exp(1.0 - t));   // mult = -2*theta, tau_ref = 1
    }
}

// ---------------- W1 transpose: g_w1t[i][o] = W1[o][i] ----------------
__global__ void transpose_kernel(const float* __restrict__ w1) {
    __shared__ float tile[32][33];
    int i0 = blockIdx.x * 32;
    int o0 = blockIdx.y * 32;
    for (int j = threadIdx.y; j < 32; j += 8)
        tile[j][threadIdx.x] = w1[(size_t)(o0 + j) * NIN + i0 + threadIdx.x];
    __syncthreads();
    for (int j = threadIdx.y; j < 32; j += 8)
        g_w1t[(size_t)(i0 + j) * NHID + o0 + threadIdx.x] = tile[threadIdx.x][j];
}

// ---------------- layer-1 GEMM exploiting binary-sparse input ----------------
// block = (b, t-group of TT=25); 512 threads, each owns 2 output rows (float2).
// Per output (o,t): sum over active i ASCENDING (order-exact vs reference).
#define ACASE(J) case J: A[J].x += w.x; A[J].y += w.y; break;

#define PROC(WREG, MREG)                                                \
    {                                                                   \
        float2 w = WREG;                                                \
        unsigned m = MREG;                                              \
        while (m) {                                                     \
            int j = __ffs(m) - 1;                                       \
            m &= m - 1;                                                 \
            switch (j) {                                                \
                ACASE(0)  ACASE(1)  ACASE(2)  ACASE(3)  ACASE(4)        \
                ACASE(5)  ACASE(6)  ACASE(7)  ACASE(8)  ACASE(9)        \
                ACASE(10) ACASE(11) ACASE(12) ACASE(13) ACASE(14)       \
                ACASE(15) ACASE(16) ACASE(17) ACASE(18) ACASE(19)       \
                ACASE(20) ACASE(21) ACASE(22) ACASE(23) ACASE(24)       \
            }                                                           \
        }                                                               \
    }

__global__ __launch_bounds__(512) void spmm1_kernel(const float* __restrict__ x) {
    __shared__ unsigned msk[NIN];
    __shared__ short    list_s[NIN];
    __shared__ unsigned mlist[NIN];
    __shared__ int      cnt_s;

    int b  = blockIdx.y;
    int t0 = blockIdx.x * TT;
    const float* xb = x + (size_t)b * NIN * TSN + t0;

    // phase 1: per-input activity bitmask over TT timesteps
    for (int i = threadIdx.x; i < NIN; i += 512) {
        const float* xr = xb + (size_t)i * TSN;
        unsigned m = 0;
#pragma unroll
        for (int j = 0; j < TT; ++j)
            if (xr[j] != 0.0f) m |= (1u << j);
        msk[i] = m;
    }
    __syncthreads();

    // phase 2: deterministic ordered compaction (warp 0)
    if (threadIdx.x < 32) {
        int lane = threadIdx.x;
        int base = 0;
        for (int c = 0; c < NIN / 32; ++c) {
            int i = c * 32 + lane;
            unsigned mv = msk[i];
            bool a = (mv != 0u);
            unsigned bal = __ballot_sync(0xffffffffu, a);
            if (a) {
                int pos = base + __popc(bal & ((1u << lane) - 1u));
                list_s[pos] = (short)i;
                mlist[pos]  = mv;
            }
            base += __popc(bal);
        }
        if (lane == 0) cnt_s = base;
    }
    __syncthreads();
    int cnt = cnt_s;

    float2 A[TT];
#pragma unroll
    for (int j = 0; j < TT; ++j) A[j] = make_float2(0.f, 0.f);

    int o2 = threadIdx.x * 2;
    const float* wbase = g_w1t + o2;

    if (cnt > 0) {
        // 4-deep software pipeline; masks for e>=cnt are 0 so the clamped
        // duplicate loads contribute nothing (order stays ascending).
#define LDC(E) (*(const float2*)(wbase + (size_t)list_s[(E) < cnt ? (E) : (cnt - 1)] * NHID))
#define MSKC(E) ((E) < cnt ? mlist[E] : 0u)
        float2 C0 = LDC(0), C1 = LDC(1), C2 = LDC(2), C3 = LDC(3);
        for (int e = 0; e < cnt; e += 4) {
            float2 N0 = LDC(e + 4), N1 = LDC(e + 5), N2 = LDC(e + 6), N3 = LDC(e + 7);
            PROC(C0, MSKC(e));
            PROC(C1, MSKC(e + 1));
            PROC(C2, MSKC(e + 2));
            PROC(C3, MSKC(e + 3));
            C0 = N0; C1 = N1; C2 = N2; C3 = N3;
        }
#undef LDC
#undef MSKC
    }

    // write out z1[b, o2+c, t0..t0+TT)
    {
        float* zr = g_z1 + ((size_t)(b * NHID + o2 + 0)) * TSN + t0;
#pragma unroll
        for (int j = 0; j < TT; ++j) zr[j] = A[j].x;
    }
    {
        float* zr = g_z1 + ((size_t)(b * NHID + o2 + 1)) * TSN + t0;
#pragma unroll
        for (int j = 0; j < TT; ++j) zr[j] = A[j].y;
    }
}

// ---------------- t-parallel 77-tap causal FIR, u written in-place into g_z1 ----------------
// Block = 2 rows x 128 threads. Row staged in smem with (r,q)-deinterleaved layout
// (phys[r][q] holds win[4q+r]) so the stride-4 window reads are conflict-free.
// Barriers are unconditional (whole block); compute/store are predicated.
#define WQ 146
__global__ __launch_bounds__(256) void conv1_kernel() {
    __shared__ float srm_s[KS];
    __shared__ float phys[2][4][WQ];

    int tid = threadIdx.x;
    int ty = tid >> 7;          // row within block
    int l  = tid & 127;

    for (int k = tid; k < KS; k += 256) srm_s[k] = g_srm[k];

    size_t row = (size_t)blockIdx.x * 2 + ty;
    float* zrow = g_z1 + row * TSN;

    // stage: win index wi in [-4, 576); win[76 + t] = z[t], zeros before
    for (int idx = l; idx < 580; idx += 128) {
        int wi = idx - 4;
        float v = 0.0f;
        if (wi >= 76 && wi < 576) v = zrow[wi - 76];
        phys[ty][idx & 3][idx >> 2] = v;
    }
    __syncthreads();

#define S(WI) phys[ty][((WI) + 4) & 3][((WI) + 4) >> 2]
    bool active = (l < 125);
    int tb = active ? l * 4 : 0;
    float u[4] = {0.f, 0.f, 0.f, 0.f};
    if (active) {
        float v[4];
        v[0] = S(tb + 76); v[1] = S(tb + 77); v[2] = S(tb + 78); v[3] = S(tb + 79);
#pragma unroll
        for (int k = 0; k < KS; ++k) {
            float w = srm_s[k];
            u[0] += w * v[0];
            u[1] += w * v[1];
            u[2] += w * v[2];
            u[3] += w * v[3];
            if (k + 1 < KS) {
                v[3] = v[2]; v[2] = v[1]; v[1] = v[0];
                v[0] = S(tb + 76 - k - 1);
            }
        }
    }
    __syncthreads();   // single, block-wide: all reads done before in-place overwrite
    if (active) {
        float4* uo = (float4*)(zrow + tb);
        *uo = make_float4(u[0], u[1], u[2], u[3]);
    }
#undef S
}

// ---------------- LIF scan (refractory feedback), one thread per row ----------------
#define LIF_STEP(UIN, SOUT)                                             \
    {                                                                   \
        float u_ = (UIN) + rb[0];                                       \
        float s_ = (u_ >= THETA) ? 1.0f : 0.0f;                         \
        _Pragma("unroll")                                               \
        for (int j_ = 0; j_ < 9; ++j_) rb[j_] = rb[j_ + 1] + s_ * rk[j_ + 1]; \
        rb[9] = s_ * rk[10];                                            \
        (SOUT) = s_;                                                    \
    }

__global__ __launch_bounds__(256) void scan1_kernel() {
    float rk[KR];
#pragma unroll
    for (int j = 0; j < KR; ++j) rk[j] = g_refk[j];

    size_t r = (size_t)blockIdx.x * blockDim.x + threadIdx.x;   // 0..65535
    const float4* u  = (const float4*)(g_z1 + r * TSN);
    float4*       sp = (float4*)(g_s1 + r * TSN);

    float rb[10];
#pragma unroll
    for (int j = 0; j < 10; ++j) rb[j] = 0.0f;

    for (int c = 0; c < TSN / 4; ++c) {
        float4 uu = u[c];
        float4 so;
        LIF_STEP(uu.x, so.x);
        LIF_STEP(uu.y, so.y);
        LIF_STEP(uu.z, so.z);
        LIF_STEP(uu.w, so.w);
        sp[c] = so;
    }
}

// ---------------- layer-2 GEMM: z2[b,o,t] = sum_i W2[o,i] * s1[b,i,t] ----------------
__global__ __launch_bounds__(320) void dense2_kernel(const float* __restrict__ w2) {
    __shared__ float ws[NOUT * NHID];
    int lt = threadIdx.y * 32 + threadIdx.x;
    for (int k = lt; k < NOUT * NHID; k += 320) ws[k] = w2[k];
    __syncthreads();

    int q = blockIdx.x * 32 + threadIdx.x;  // float4 index along t, 0..124
    if (q >= TSN / 4) return;
    int o = threadIdx.y;
    int b = blockIdx.y;

    const float4* s1b = ((const float4*)(g_s1 + (size_t)b * NHID * TSN)) + q;
    const float*  wr  = ws + o * NHID;

    float4 acc = make_float4(0.f, 0.f, 0.f, 0.f);
#pragma unroll 8
    for (int i = 0; i < NHID; ++i) {
        float w = wr[i];
        float4 s = s1b[(size_t)i * (TSN / 4)];
        acc.x += w * s.x; acc.y += w * s.y; acc.z += w * s.z; acc.w += w * s.w;
    }
    float4* zo = ((float4*)(g_z2 + ((size_t)(b * NOUT + o)) * TSN)) + q;
    *zo = acc;
}

// ---------------- layer-2 conv (t-parallel) ----------------
__global__ void conv2_kernel() {
    __shared__ float srm_s[KS];
    for (int k = threadIdx.x; k < KS; k += blockDim.x) srm_s[k] = g_srm[k];
    __syncthreads();

    int idx = blockIdx.x * blockDim.x + threadIdx.x;
    int nc = TSN / 4;
    int total = BB * NOUT * nc;
    if (idx >= total) return;
    int r = idx / nc, c = idx % nc;
    const float* z = g_z2 + (size_t)r * TSN;
    int tb = c * 4;
    float u0 = 0.f, u1 = 0.f, u2 = 0.f, u3 = 0.f;
    for (int k = 0; k < KS; ++k) {
        float w = srm_s[k];
        int t = tb - k;
        if (t + 3 >= 0) {
            if (t     >= 0) u0 += w * z[t];
            if (t + 1 >= 0) u1 += w * z[t + 1];
            if (t + 2 >= 0) u2 += w * z[t + 2];
            u3 += w * z[t + 3];
        }
    }
    float* uo = g_u2 + (size_t)r * TSN + tb;
    uo[0] = u0; uo[1] = u1; uo[2] = u2; uo[3] = u3;
}

// ---------------- layer-2 LIF scan -> final output ----------------
__global__ void scan2_kernel(float* __restrict__ out) {
    float rk[KR];
#pragma unroll
    for (int j = 0; j < KR; ++j) rk[j] = g_refk[j];

    int r = blockIdx.x * blockDim.x + threadIdx.x;
    if (r >= BB * NOUT) return;
    const float* u = g_u2 + (size_t)r * TSN;
    float* o = out + (size_t)r * TSN;

    float rb[10];
#pragma unroll
    for (int j = 0; j < 10; ++j) rb[j] = 0.0f;

    for (int t = 0; t < TSN; ++t) {
        float s;
        LIF_STEP(u[t], s);
        o[t] = s;
    }
}

// ---------------- launcher ----------------
extern "C" void kernel_launch(void* const* d_in, const int* in_sizes, int n_in,
                              void* d_out, int out_size) {
    const float* x  = (const float*)d_in[0];   // spike_input [64,1024,500]
    const float* w1 = (const float*)d_in[1];   // W1 [1024,1024]
    const float* w2 = (const float*)d_in[2];   // W2 [10,1024]
    float* out = (float*)d_out;                // s2 [64,10,500]

    init_kernel<<<1, 128>>>();
    transpose_kernel<<<dim3(32, 32), dim3(32, 8)>>>(w1);
    spmm1_kernel<<<dim3(NTG, BB), 512>>>(x);
    conv1_kernel<<<BB * NHID / 2, 256>>>();
    scan1_kernel<<<BB * NHID / 256, 256>>>();
    dense2_kernel<<<dim3(4, BB), dim3(32, 10)>>>(w2);
    conv2_kernel<<<(BB * NOUT * (TSN / 4) + 255) / 256, 256>>>();
    scan2_kernel<<<(BB * NOUT + 255) / 256, 256>>>(out);
}

// round 5
// speedup vs baseline: 1.4846x; 1.4846x over previous
#include <cuda_runtime.h>
#include <math.h>

// ---------------- problem constants ----------------
#define BB    64
#define NIN   1024
#define NHID  1024
#define NOUT  10
#define TSN   500          // time bins
#define KS    77           // SRM kernel taps (truncated alpha kernel, tau=10)
#define KR    11           // refractory kernel taps (tau=1), REF[0]==0
#define THETA 10.0f
#define TT    20           // timesteps per spmm block
#define NTG   (TSN / TT)   // 25

// ---------------- scratch (static device memory; no allocations) ----------------
__device__ float g_srm[KS];
__device__ float g_refk[KR];
__device__ float g_w1t[(size_t)NIN * NHID];          // 4 MB, W1 transposed [i][o]
__device__ float g_z1[(size_t)BB * NHID * TSN];      // 131 MB (z, then u in-place)
__device__ float g_s1[(size_t)BB * NHID * TSN];      // 131 MB
__device__ float g_z2[(size_t)BB * NOUT * TSN];      // 1.28 MB
__device__ float g_u2[(size_t)BB * NOUT * TSN];      // 1.28 MB
__device__ float g_dummy[32];

// ---------------- kernel tap init (double, matches python math.exp -> f32) ----------------
__global__ void init_kernel() {
    int i = threadIdx.x;
    if (i < KS) {
        double t = (double)i;
        g_srm[i] = (float)(t / 10.0 * exp(1.0 - t / 10.0));
    }
    if (i < KR) {
        double t = (double)i;
        g_refk[i] = (float)(-20.0 * t * exp(1.0 - t));   // mult = -2*theta, tau_ref = 1
    }
}

// ---------------- W1 transpose: g_w1t[i][o] = W1[o][i] ----------------
__global__ void transpose_kernel(const float* __restrict__ w1) {
    __shared__ float tile[32][33];
    int i0 = blockIdx.x * 32;
    int o0 = blockIdx.y * 32;
    for (int j = threadIdx.y; j < 32; j += 8)
        tile[j][threadIdx.x] = w1[(size_t)(o0 + j) * NIN + i0 + threadIdx.x];
    __syncthreads();
    for (int j = threadIdx.y; j < 32; j += 8)
        g_w1t[(size_t)(i0 + j) * NHID + o0 + threadIdx.x] = tile[threadIdx.x][j];
}

// ---------------- dummy (shifts launch index so ncu's capture lands on spmm1) ----------------
__global__ void dummy_kernel() {
    if (threadIdx.x < 32) g_dummy[threadIdx.x] = (float)threadIdx.x;
}

// ---------------- layer-1 GEMM exploiting binary-sparse input ----------------
// block = (b, t-group of TT=20); 256 threads, each owns 4 output rows (float4).
// Per output (o,t): sum over active i ASCENDING (order-exact vs reference).
#define ACASE(J) case J: A[J].x += w.x; A[J].y += w.y; A[J].z += w.z; A[J].w += w.w; break;

#define PROC(WREG, MREG)                                                \
    {                                                                   \
        float4 w = WREG;                                                \
        unsigned m = MREG;                                              \
        while (m) {                                                     \
            int j = __ffs(m) - 1;                                       \
            m &= m - 1;                                                 \
            switch (j) {                                                \
                ACASE(0)  ACASE(1)  ACASE(2)  ACASE(3)  ACASE(4)        \
                ACASE(5)  ACASE(6)  ACASE(7)  ACASE(8)  ACASE(9)        \
                ACASE(10) ACASE(11) ACASE(12) ACASE(13) ACASE(14)       \
                ACASE(15) ACASE(16) ACASE(17) ACASE(18) ACASE(19)       \
            }                                                           \
        }                                                               \
    }

__global__ __launch_bounds__(256, 2) void spmm1_kernel(const float* __restrict__ x) {
    __shared__ unsigned msk[NIN];
    __shared__ short    list_s[NIN + 8];
    __shared__ unsigned mlist[NIN + 8];
    __shared__ int      cnt_s;

    int b  = blockIdx.y;
    int t0 = blockIdx.x * TT;
    const float* xb = x + (size_t)b * NIN * TSN + t0;

    // phase 1: per-input activity bitmask over TT timesteps
    for (int i = threadIdx.x; i < NIN; i += 256) {
        const float* xr = xb + (size_t)i * TSN;
        unsigned m = 0;
#pragma unroll
        for (int j = 0; j < TT; ++j)
            if (xr[j] != 0.0f) m |= (1u << j);
        msk[i] = m;
    }
    __syncthreads();

    // phase 2: deterministic ordered compaction (warp 0), then pad 8 safe entries
    if (threadIdx.x < 32) {
        int lane = threadIdx.x;
        int base = 0;
        for (int c = 0; c < NIN / 32; ++c) {
            int i = c * 32 + lane;
            unsigned mv = msk[i];
            bool a = (mv != 0u);
            unsigned bal = __ballot_sync(0xffffffffu, a);
            if (a) {
                int pos = base + __popc(bal & ((1u << lane) - 1u));
                list_s[pos] = (short)i;
                mlist[pos]  = mv;
            }
            base += __popc(bal);
        }
        if (lane < 8) {                 // padding: index 0 (valid), mask 0 (no-op)
            list_s[base + lane] = 0;
            mlist[base + lane]  = 0u;
        }
        if (lane == 0) cnt_s = base;
    }
    __syncthreads();
    int cnt = cnt_s;

    float4 A[TT];
#pragma unroll
    for (int j = 0; j < TT; ++j) A[j] = make_float4(0.f, 0.f, 0.f, 0.f);

    int o4 = threadIdx.x * 4;
    const float* wbase = g_w1t + o4;

    // depth-2 rotating prefetch; padded list makes all indices safe.
#define LDE(E) (*(const float4*)(wbase + (size_t)list_s[E] * NHID))
    float4 W0 = LDE(0);
    float4 W1 = LDE(1);
    for (int e = 0; e < cnt; e += 2) {
        float4 P0 = LDE(e + 2);
        PROC(W0, mlist[e]);
        float4 P1 = LDE(e + 3);
        PROC(W1, mlist[e + 1]);
        W0 = P0; W1 = P1;
    }
#undef LDE

    // write out z1[b, o4+c, t0..t0+TT) — direct register-component stores
    {
        float* zr = g_z1 + ((size_t)(b * NHID + o4 + 0)) * TSN + t0;
#pragma unroll
        for (int j = 0; j < TT; ++j) zr[j] = A[j].x;
    }
    {
        float* zr = g_z1 + ((size_t)(b * NHID + o4 + 1)) * TSN + t0;
#pragma unroll
        for (int j = 0; j < TT; ++j) zr[j] = A[j].y;
    }
    {
        float* zr = g_z1 + ((size_t)(b * NHID + o4 + 2)) * TSN + t0;
#pragma unroll
        for (int j = 0; j < TT; ++j) zr[j] = A[j].z;
    }
    {
        float* zr = g_z1 + ((size_t)(b * NHID + o4 + 3)) * TSN + t0;
#pragma unroll
        for (int j = 0; j < TT; ++j) zr[j] = A[j].w;
    }
}

// ---------------- t-parallel 77-tap causal FIR, u written in-place into g_z1 ----------------
// Block = 2 rows x 128 threads. Row staged in smem with (r,q)-deinterleaved layout
// (phys[r][q] holds win[4q+r]) so the stride-4 window reads are conflict-free.
// Barriers are unconditional (whole block); compute/store are predicated.
#define WQ 146
__global__ __launch_bounds__(256) void conv1_kernel() {
    __shared__ float srm_s[KS];
    __shared__ float phys[2][4][WQ];

    int tid = threadIdx.x;
    int ty = tid >> 7;          // row within block
    int l  = tid & 127;

    for (int k = tid; k < KS; k += 256) srm_s[k] = g_srm[k];

    size_t row = (size_t)blockIdx.x * 2 + ty;
    float* zrow = g_z1 + row * TSN;

    // stage: win index wi in [-4, 576); win[76 + t] = z[t], zeros before
    for (int idx = l; idx < 580; idx += 128) {
        int wi = idx - 4;
        float v = 0.0f;
        if (wi >= 76 && wi < 576) v = zrow[wi - 76];
        phys[ty][idx & 3][idx >> 2] = v;
    }
    __syncthreads();

#define S(WI) phys[ty][((WI) + 4) & 3][((WI) + 4) >> 2]
    bool active = (l < 125);
    int tb = active ? l * 4 : 0;
    float u[4] = {0.f, 0.f, 0.f, 0.f};
    if (active) {
        float v[4];
        v[0] = S(tb + 76); v[1] = S(tb + 77); v[2] = S(tb + 78); v[3] = S(tb + 79);
#pragma unroll
        for (int k = 0; k < KS; ++k) {
            float w = srm_s[k];
            u[0] += w * v[0];
            u[1] += w * v[1];
            u[2] += w * v[2];
            u[3] += w * v[3];
            if (k + 1 < KS) {
                v[3] = v[2]; v[2] = v[1]; v[1] = v[0];
                v[0] = S(tb + 76 - k - 1);
            }
        }
    }
    __syncthreads();   // single, block-wide: all reads done before in-place overwrite
    if (active) {
        float4* uo = (float4*)(zrow + tb);
        *uo = make_float4(u[0], u[1], u[2], u[3]);
    }
#undef S
}

// ---------------- LIF scan (refractory feedback), one thread per row ----------------
#define LIF_STEP(UIN, SOUT)                                             \
    {                                                                   \
        float u_ = (UIN) + rb[0];                                       \
        float s_ = (u_ >= THETA) ? 1.0f : 0.0f;                         \
        _Pragma("unroll")                                               \
        for (int j_ = 0; j_ < 9; ++j_) rb[j_] = rb[j_ + 1] + s_ * rk[j_ + 1]; \
        rb[9] = s_ * rk[10];                                            \
        (SOUT) = s_;                                                    \
    }

__global__ __launch_bounds__(256) void scan1_kernel() {
    float rk[KR];
#pragma unroll
    for (int j = 0; j < KR; ++j) rk[j] = g_refk[j];

    size_t r = (size_t)blockIdx.x * blockDim.x + threadIdx.x;   // 0..65535
    const float4* u  = (const float4*)(g_z1 + r * TSN);
    float4*       sp = (float4*)(g_s1 + r * TSN);

    float rb[10];
#pragma unroll
    for (int j = 0; j < 10; ++j) rb[j] = 0.0f;

    for (int c = 0; c < TSN / 4; ++c) {
        float4 uu = u[c];
        float4 so;
        LIF_STEP(uu.x, so.x);
        LIF_STEP(uu.y, so.y);
        LIF_STEP(uu.z, so.z);
        LIF_STEP(uu.w, so.w);
        sp[c] = so;
    }
}

// ---------------- layer-2 GEMM: z2[b,o,t] = sum_i W2[o,i] * s1[b,i,t] ----------------
__global__ __launch_bounds__(320) void dense2_kernel(const float* __restrict__ w2) {
    __shared__ float ws[NOUT * NHID];
    int lt = threadIdx.y * 32 + threadIdx.x;
    for (int k = lt; k < NOUT * NHID; k += 320) ws[k] = w2[k];
    __syncthreads();

    int q = blockIdx.x * 32 + threadIdx.x;  // float4 index along t, 0..124
    if (q >= TSN / 4) return;
    int o = threadIdx.y;
    int b = blockIdx.y;

    const float4* s1b = ((const float4*)(g_s1 + (size_t)b * NHID * TSN)) + q;
    const float*  wr  = ws + o * NHID;

    float4 acc = make_float4(0.f, 0.f, 0.f, 0.f);
#pragma unroll 8
    for (int i = 0; i < NHID; ++i) {
        float w = wr[i];
        float4 s = s1b[(size_t)i * (TSN / 4)];
        acc.x += w * s.x; acc.y += w * s.y; acc.z += w * s.z; acc.w += w * s.w;
    }
    float4* zo = ((float4*)(g_z2 + ((size_t)(b * NOUT + o)) * TSN)) + q;
    *zo = acc;
}

// ---------------- layer-2 conv (t-parallel) ----------------
__global__ void conv2_kernel() {
    __shared__ float srm_s[KS];
    for (int k = threadIdx.x; k < KS; k += blockDim.x) srm_s[k] = g_srm[k];
    __syncthreads();

    int idx = blockIdx.x * blockDim.x + threadIdx.x;
    int nc = TSN / 4;
    int total = BB * NOUT * nc;
    if (idx >= total) return;
    int r = idx / nc, c = idx % nc;
    const float* z = g_z2 + (size_t)r * TSN;
    int tb = c * 4;
    float u0 = 0.f, u1 = 0.f, u2 = 0.f, u3 = 0.f;
    for (int k = 0; k < KS; ++k) {
        float w = srm_s[k];
        int t = tb - k;
        if (t + 3 >= 0) {
            if (t     >= 0) u0 += w * z[t];
            if (t + 1 >= 0) u1 += w * z[t + 1];
            if (t + 2 >= 0) u2 += w * z[t + 2];
            u3 += w * z[t + 3];
        }
    }
    float* uo = g_u2 + (size_t)r * TSN + tb;
    uo[0] = u0; uo[1] = u1; uo[2] = u2; uo[3] = u3;
}

// ---------------- layer-2 LIF scan -> final output ----------------
__global__ void scan2_kernel(float* __restrict__ out) {
    float rk[KR];
#pragma unroll
    for (int j = 0; j < KR; ++j) rk[j] = g_refk[j];

    int r = blockIdx.x * blockDim.x + threadIdx.x;
    if (r >= BB * NOUT) return;
    const float* u = g_u2 + (size_t)r * TSN;
    float* o = out + (size_t)r * TSN;

    float rb[10];
#pragma unroll
    for (int j = 0; j < 10; ++j) rb[j] = 0.0f;

    for (int t = 0; t < TSN; ++t) {
        float s;
        LIF_STEP(u[t], s);
        o[t] = s;
    }
}

// ---------------- launcher ----------------
extern "C" void kernel_launch(void* const* d_in, const int* in_sizes, int n_in,
                              void* d_out, int out_size) {
    const float* x  = (const float*)d_in[0];   // spike_input [64,1024,500]
    const float* w1 = (const float*)d_in[1];   // W1 [1024,1024]
    const float* w2 = (const float*)d_in[2];   // W2 [10,1024]
    float* out = (float*)d_out;                // s2 [64,10,500]

    init_kernel<<<1, 128>>>();                              // launch 1
    transpose_kernel<<<dim3(32, 32), dim3(32, 8)>>>(w1);    // launch 2
    dummy_kernel<<<1, 32>>>();                              // launch 3 (profiler shim)
    spmm1_kernel<<<dim3(NTG, BB), 256>>>(x);                // launch 4 <- ncu capture
    conv1_kernel<<<BB * NHID / 2, 256>>>();                 // launch 5
    scan1_kernel<<<BB * NHID / 256, 256>>>();               // launch 6
    dense2_kernel<<<dim3(4, BB), dim3(32, 10)>>>(w2);       // launch 7
    conv2_kernel<<<(BB * NOUT * (TSN / 4) + 255) / 256, 256>>>();  // launch 8
    scan2_kernel<<<(BB * NOUT + 255) / 256, 256>>>(out);    // launch 9
}

// round 6
// speedup vs baseline: 1.7076x; 1.1502x over previous
#include <cuda_runtime.h>
#include <math.h>

// ---------------- problem constants ----------------
#define BB    64
#define NIN   1024
#define NHID  1024
#define NOUT  10
#define TSN   500          // time bins
#define KS    77           // SRM kernel taps (truncated alpha kernel, tau=10)
#define KR    11           // refractory kernel taps (tau=1), REF[0]==0
#define THETA 10.0f
#define TT    20           // timesteps per spmm block
#define NTG   (TSN / TT)   // 25

// ---------------- scratch (static device memory; no allocations) ----------------
__device__ float g_srm[KS];
__device__ float g_refk[KR];
__device__ float g_w1t[(size_t)NIN * NHID];              // 4 MB, W1 transposed [i][o]
__device__ float g_z1[(size_t)BB * NHID * TSN];          // 131 MB (z, then u in-place)
__device__ unsigned char g_s1[(size_t)BB * NHID * TSN];  // 33 MB (binary spikes as u8)
__device__ float g_z2[(size_t)BB * NOUT * TSN];          // 1.28 MB
__device__ float g_u2[(size_t)BB * NOUT * TSN];          // 1.28 MB
__device__ float g_dummy[32];

// ---------------- kernel tap init (double, matches python math.exp -> f32) ----------------
__global__ void init_kernel() {
    int i = threadIdx.x;
    if (i < KS) {
        double t = (double)i;
        g_srm[i] = (float)(t / 10.0 * exp(1.0 - t / 10.0));
    }
    if (i < KR) {
        double t = (double)i;
        g_refk[i] = (float)(-20.0 * t * exp(1.0 - t));   // mult = -2*theta, tau_ref = 1
    }
}

// ---------------- W1 transpose: g_w1t[i][o] = W1[o][i] ----------------
__global__ void transpose_kernel(const float* __restrict__ w1) {
    __shared__ float tile[32][33];
    int i0 = blockIdx.x * 32;
    int o0 = blockIdx.y * 32;
    for (int j = threadIdx.y; j < 32; j += 8)
        tile[j][threadIdx.x] = w1[(size_t)(o0 + j) * NIN + i0 + threadIdx.x];
    __syncthreads();
    for (int j = threadIdx.y; j < 32; j += 8)
        g_w1t[(size_t)(i0 + j) * NHID + o0 + threadIdx.x] = tile[threadIdx.x][j];
}

// ---------------- dummy (shifts launch index so ncu's capture lands on spmm1) ----------------
__global__ void dummy_kernel() {
    if (threadIdx.x < 32) g_dummy[threadIdx.x] = (float)threadIdx.x;
}

// ---------------- layer-1 GEMM exploiting binary-sparse input ----------------
// block = (b, t-group of TT=20); 512 threads, each owns 2 output rows (float2).
// Per output (o,t): sum over active i ASCENDING (order-exact vs reference).
#define ACASE(J) case J: A[J].x += w.x; A[J].y += w.y; break;

#define PROC(WREG, MREG)                                                \
    {                                                                   \
        float2 w = WREG;                                                \
        unsigned m = MREG;                                              \
        while (m) {                                                     \
            int j = __ffs(m) - 1;                                       \
            m &= m - 1;                                                 \
            switch (j) {                                                \
                ACASE(0)  ACASE(1)  ACASE(2)  ACASE(3)  ACASE(4)        \
                ACASE(5)  ACASE(6)  ACASE(7)  ACASE(8)  ACASE(9)        \
                ACASE(10) ACASE(11) ACASE(12) ACASE(13) ACASE(14)       \
                ACASE(15) ACASE(16) ACASE(17) ACASE(18) ACASE(19)       \
            }                                                           \
        }                                                               \
    }

__global__ __launch_bounds__(512, 2) void spmm1_kernel(const float* __restrict__ x) {
    __shared__ unsigned msk[NIN];
    __shared__ unsigned long long plist[NIN + 8];   // (i << 32) | mask, i-ascending
    __shared__ int cnt_s;
    __shared__ float wb[TT][257];                   // staged coalesced writes

    int b  = blockIdx.y;
    int t0 = blockIdx.x * TT;
    const float* xb = x + (size_t)b * NIN * TSN + t0;

    // phase 1: per-input activity bitmask over TT timesteps (vectorized; t0*4 is 16B-aligned)
    for (int i = threadIdx.x; i < NIN; i += 512) {
        const float4* xr = (const float4*)(xb + (size_t)i * TSN);
        unsigned m = 0;
#pragma unroll
        for (int j4 = 0; j4 < TT / 4; ++j4) {
            float4 v = xr[j4];
            if (v.x != 0.0f) m |= 1u << (j4 * 4 + 0);
            if (v.y != 0.0f) m |= 1u << (j4 * 4 + 1);
            if (v.z != 0.0f) m |= 1u << (j4 * 4 + 2);
            if (v.w != 0.0f) m |= 1u << (j4 * 4 + 3);
        }
        msk[i] = m;
    }
    __syncthreads();

    // phase 2: deterministic ordered compaction (warp 0), then pad 8 safe entries
    if (threadIdx.x < 32) {
        int lane = threadIdx.x;
        int base = 0;
        for (int c = 0; c < NIN / 32; ++c) {
            int i = c * 32 + lane;
            unsigned mv = msk[i];
            bool a = (mv != 0u);
            unsigned bal = __ballot_sync(0xffffffffu, a);
            if (a) {
                int pos = base + __popc(bal & ((1u << lane) - 1u));
                plist[pos] = ((unsigned long long)i << 32) | mv;
            }
            base += __popc(bal);
        }
        if (lane < 8) plist[base + lane] = 0ULL;   // idx 0 (valid), mask 0 (no-op)
        if (lane == 0) cnt_s = base;
    }
    __syncthreads();
    int cnt = cnt_s;

    float2 A[TT];
#pragma unroll
    for (int j = 0; j < TT; ++j) A[j] = make_float2(0.f, 0.f);

    int o2 = threadIdx.x * 2;
    const float* wbase = g_w1t + o2;

    // depth-2 rotating prefetch; padded list makes all indices safe.
#define LDW(E) (*(const float2*)(wbase + (size_t)((E) >> 32) * NHID))
    unsigned long long E0 = plist[0], E1 = plist[1];
    float2 W0 = LDW(E0);
    float2 W1 = LDW(E1);
    for (int e = 0; e < cnt; e += 2) {
        unsigned long long E2 = plist[e + 2], E3 = plist[e + 3];
        float2 P0 = LDW(E2);
        PROC(W0, (unsigned)E0);
        float2 P1 = LDW(E3);
        PROC(W1, (unsigned)E1);
        W0 = P0; W1 = P1; E0 = E2; E1 = E3;
    }
#undef LDW

    // staged coalesced writes: 4 quarters of 256 outputs
#pragma unroll 1
    for (int q = 0; q < 4; ++q) {
        __syncthreads();                 // previous quarter's stores done
        if ((threadIdx.x >> 7) == q) {
            int ol = (threadIdx.x & 127) * 2;
#pragma unroll
            for (int j = 0; j < TT; ++j) { wb[j][ol] = A[j].x; wb[j][ol + 1] = A[j].y; }
        }
        __syncthreads();
        int obase = b * NHID + q * 256;
        for (int idx = threadIdx.x; idx < 256 * TT; idx += 512) {
            int oo = idx / TT, j = idx - oo * TT;
            g_z1[(size_t)(obase + oo) * TSN + t0 + j] = wb[j][oo];
        }
    }
}

// ---------------- t-parallel 77-tap causal FIR, u written in-place into g_z1 ----------------
// Block = 2 rows x 128 threads. Row staged in smem with (r,q)-deinterleaved layout
// (phys[r][q] holds win[4q+r]) so the stride-4 window reads are conflict-free.
// Barriers are unconditional (whole block); compute/store are predicated.
#define WQ 146
__global__ __launch_bounds__(256) void conv1_kernel() {
    __shared__ float srm_s[KS];
    __shared__ float phys[2][4][WQ];

    int tid = threadIdx.x;
    int ty = tid >> 7;          // row within block
    int l  = tid & 127;

    for (int k = tid; k < KS; k += 256) srm_s[k] = g_srm[k];

    size_t row = (size_t)blockIdx.x * 2 + ty;
    float* zrow = g_z1 + row * TSN;

    // stage: win index wi in [-4, 576); win[76 + t] = z[t], zeros before
    for (int idx = l; idx < 580; idx += 128) {
        int wi = idx - 4;
        float v = 0.0f;
        if (wi >= 76 && wi < 576) v = zrow[wi - 76];
        phys[ty][idx & 3][idx >> 2] = v;
    }
    __syncthreads();

#define S(WI) phys[ty][((WI) + 4) & 3][((WI) + 4) >> 2]
    bool active = (l < 125);
    int tb = active ? l * 4 : 0;
    float u[4] = {0.f, 0.f, 0.f, 0.f};
    if (active) {
        float v[4];
        v[0] = S(tb + 76); v[1] = S(tb + 77); v[2] = S(tb + 78); v[3] = S(tb + 79);
#pragma unroll
        for (int k = 0; k < KS; ++k) {
            float w = srm_s[k];
            u[0] += w * v[0];
            u[1] += w * v[1];
            u[2] += w * v[2];
            u[3] += w * v[3];
            if (k + 1 < KS) {
                v[3] = v[2]; v[2] = v[1]; v[1] = v[0];
                v[0] = S(tb + 76 - k - 1);
            }
        }
    }
    __syncthreads();   // single, block-wide: all reads done before in-place overwrite
    if (active) {
        float4* uo = (float4*)(zrow + tb);
        *uo = make_float4(u[0], u[1], u[2], u[3]);
    }
#undef S
}

// ---------------- LIF scan (refractory feedback), one thread per row; u8 spike out ----------------
#define LIF_STEP(UIN, SOUT)                                             \
    {                                                                   \
        float u_ = (UIN) + rb[0];                                       \
        float s_ = (u_ >= THETA) ? 1.0f : 0.0f;                         \
        _Pragma("unroll")                                               \
        for (int j_ = 0; j_ < 9; ++j_) rb[j_] = rb[j_ + 1] + s_ * rk[j_ + 1]; \
        rb[9] = s_ * rk[10];                                            \
        (SOUT) = s_;                                                    \
    }

__global__ __launch_bounds__(256) void scan1_kernel() {
    float rk[KR];
#pragma unroll
    for (int j = 0; j < KR; ++j) rk[j] = g_refk[j];

    size_t r = (size_t)blockIdx.x * blockDim.x + threadIdx.x;   // 0..65535
    const float4* u  = (const float4*)(g_z1 + r * TSN);
    uchar4*      sp = (uchar4*)(g_s1 + r * TSN);

    float rb[10];
#pragma unroll
    for (int j = 0; j < 10; ++j) rb[j] = 0.0f;

    for (int c = 0; c < TSN / 4; ++c) {
        float4 uu = u[c];
        float s0, s1v, s2v, s3;
        LIF_STEP(uu.x, s0);
        LIF_STEP(uu.y, s1v);
        LIF_STEP(uu.z, s2v);
        LIF_STEP(uu.w, s3);
        uchar4 so;
        so.x = (unsigned char)s0;
        so.y = (unsigned char)s1v;
        so.z = (unsigned char)s2v;
        so.w = (unsigned char)s3;
        sp[c] = so;
    }
}

// ---------------- layer-2 GEMM: z2[b,o,t] = sum_i W2[o,i] * s1[b,i,t] (s1 is u8 0/1) ----------------
__global__ __launch_bounds__(320) void dense2_kernel(const float* __restrict__ w2) {
    __shared__ float ws[NOUT * NHID];
    int lt = threadIdx.y * 32 + threadIdx.x;
    for (int k = lt; k < NOUT * NHID; k += 320) ws[k] = w2[k];
    __syncthreads();

    int q = blockIdx.x * 32 + threadIdx.x;  // uchar4 index along t, 0..124
    if (q >= TSN / 4) return;
    int o = threadIdx.y;
    int b = blockIdx.y;

    const uchar4* s1b = ((const uchar4*)(g_s1 + (size_t)b * NHID * TSN)) + q;
    const float*  wr  = ws + o * NHID;

    float4 acc = make_float4(0.f, 0.f, 0.f, 0.f);
#pragma unroll 8
    for (int i = 0; i < NHID; ++i) {
        float w = wr[i];
        uchar4 s = s1b[(size_t)i * (TSN / 4)];
        acc.x += w * (float)s.x;
        acc.y += w * (float)s.y;
        acc.z += w * (float)s.z;
        acc.w += w * (float)s.w;
    }
    float4* zo = ((float4*)(g_z2 + ((size_t)(b * NOUT + o)) * TSN)) + q;
    *zo = acc;
}

// ---------------- layer-2 conv (t-parallel) ----------------
__global__ void conv2_kernel() {
    __shared__ float srm_s[KS];
    for (int k = threadIdx.x; k < KS; k += blockDim.x) srm_s[k] = g_srm[k];
    __syncthreads();

    int idx = blockIdx.x * blockDim.x + threadIdx.x;
    int nc = TSN / 4;
    int total = BB * NOUT * nc;
    if (idx >= total) return;
    int r = idx / nc, c = idx % nc;
    const float* z = g_z2 + (size_t)r * TSN;
    int tb = c * 4;
    float u0 = 0.f, u1 = 0.f, u2 = 0.f, u3 = 0.f;
    for (int k = 0; k < KS; ++k) {
        float w = srm_s[k];
        int t = tb - k;
        if (t + 3 >= 0) {
            if (t     >= 0) u0 += w * z[t];
            if (t + 1 >= 0) u1 += w * z[t + 1];
            if (t + 2 >= 0) u2 += w * z[t + 2];
            u3 += w * z[t + 3];
        }
    }
    float* uo = g_u2 + (size_t)r * TSN + tb;
    uo[0] = u0; uo[1] = u1; uo[2] = u2; uo[3] = u3;
}

// ---------------- layer-2 LIF scan -> final output ----------------
__global__ void scan2_kernel(float* __restrict__ out) {
    float rk[KR];
#pragma unroll
    for (int j = 0; j < KR; ++j) rk[j] = g_refk[j];

    int r = blockIdx.x * blockDim.x + threadIdx.x;
    if (r >= BB * NOUT) return;
    const float* u = g_u2 + (size_t)r * TSN;
    float* o = out + (size_t)r * TSN;

    float rb[10];
#pragma unroll
    for (int j = 0; j < 10; ++j) rb[j] = 0.0f;

    for (int t = 0; t < TSN; ++t) {
        float s;
        LIF_STEP(u[t], s);
        o[t] = s;
    }
}

// ---------------- launcher ----------------
extern "C" void kernel_launch(void* const* d_in, const int* in_sizes, int n_in,
                              void* d_out, int out_size) {
    const float* x  = (const float*)d_in[0];   // spike_input [64,1024,500]
    const float* w1 = (const float*)d_in[1];   // W1 [1024,1024]
    const float* w2 = (const float*)d_in[2];   // W2 [10,1024]
    float* out = (float*)d_out;                // s2 [64,10,500]

    init_kernel<<<1, 128>>>();                              // launch 1
    transpose_kernel<<<dim3(32, 32), dim3(32, 8)>>>(w1);    // launch 2
    dummy_kernel<<<1, 32>>>();                              // launch 3 (profiler shim)
    spmm1_kernel<<<dim3(NTG, BB), 512>>>(x);                // launch 4 <- ncu capture
    conv1_kernel<<<BB * NHID / 2, 256>>>();                 // launch 5
    scan1_kernel<<<BB * NHID / 256, 256>>>();               // launch 6
    dense2_kernel<<<dim3(4, BB), dim3(32, 10)>>>(w2);       // launch 7
    conv2_kernel<<<(BB * NOUT * (TSN / 4) + 255) / 256, 256>>>();  // launch 8
    scan2_kernel<<<(BB * NOUT + 255) / 256, 256>>>(out);    // launch 9
}

// round 7
// speedup vs baseline: 2.9712x; 1.7400x over previous
#include <cuda_runtime.h>
#include <math.h>

// ---------------- problem constants ----------------
#define BB    64
#define NIN   1024
#define NHID  1024
#define NOUT  10
#define TSN   500          // time bins
#define KS    77           // SRM kernel taps (truncated alpha kernel, tau=10)
#define KR    11           // refractory kernel taps (tau=1), REF[0]==0
#define THETA 10.0f
#define TT    20           // timesteps per spmm block
#define NTG   (TSN / TT)   // 25
#define TCAP  384          // per-t event list capacity (mean 51, sigma 7)

// ---------------- scratch (static device memory; no allocations) ----------------
__device__ float g_srm[KS];
__device__ float g_refk[KR];
__device__ float g_w1t[(size_t)(NIN + 1) * NHID];        // W1^T [i][o]; row NIN is all-zero (pad row)
__device__ float g_z1[(size_t)BB * NHID * TSN];          // 131 MB (z, then u in-place)
__device__ unsigned char g_s1[(size_t)BB * NHID * TSN];  // 33 MB (binary spikes as u8)
__device__ float g_z2[(size_t)BB * NOUT * TSN];          // 1.28 MB
__device__ float g_u2[(size_t)BB * NOUT * TSN];          // 1.28 MB
__device__ float g_dummy[32];

// ---------------- kernel tap init (double, matches python math.exp -> f32) ----------------
__global__ void init_kernel() {
    int i = threadIdx.x;
    if (i < KS) {
        double t = (double)i;
        g_srm[i] = (float)(t / 10.0 * exp(1.0 - t / 10.0));
    }
    if (i < KR) {
        double t = (double)i;
        g_refk[i] = (float)(-20.0 * t * exp(1.0 - t));   // mult = -2*theta, tau_ref = 1
    }
    // zero pad row of W1^T (used by event-list padding)
    for (int k = threadIdx.x; k < NHID; k += blockDim.x)
        g_w1t[(size_t)NIN * NHID + k] = 0.0f;
}

// ---------------- W1 transpose: g_w1t[i][o] = W1[o][i] ----------------
__global__ void transpose_kernel(const float* __restrict__ w1) {
    __shared__ float tile[32][33];
    int i0 = blockIdx.x * 32;
    int o0 = blockIdx.y * 32;
    for (int j = threadIdx.y; j < 32; j += 8)
        tile[j][threadIdx.x] = w1[(size_t)(o0 + j) * NIN + i0 + threadIdx.x];
    __syncthreads();
    for (int j = threadIdx.y; j < 32; j += 8)
        g_w1t[(size_t)(i0 + j) * NHID + o0 + threadIdx.x] = tile[threadIdx.x][j];
}

// ---------------- dummy (shifts launch index so ncu's capture lands on spmm1) ----------------
__global__ void dummy_kernel() {
    if (threadIdx.x < 32) g_dummy[threadIdx.x] = (float)threadIdx.x;
}

// ---------------- layer-1 GEMM via per-timestep event lists ----------------
// block = (b, t-group of TT=20); 512 threads, each owns 2 output rows (o2, o2+1).
// For each t: z1[b,o,t0+t] = sum over active i ASCENDING of W1[o,i]  (order-exact).
// Branchless inner loop: ushort4 index fetch -> 4 x LDG.64 -> 8 FADD, 4-deep prefetch.
// Lists padded with index NIN (all-zero W row) so no guards are needed; +0.0f adds
// are exact no-ops on these finite sums.
__global__ __launch_bounds__(512, 2) void spmm1_kernel(const float* __restrict__ x) {
    __shared__ unsigned msk[NIN];
    __shared__ unsigned short tl[TT][TCAP];
    __shared__ int tcnt[TT];
    __shared__ float wb[10][513];

    int b  = blockIdx.y;
    int t0 = blockIdx.x * TT;
    const float* xb = x + (size_t)b * NIN * TSN + t0;

    // phase 1: per-input activity bitmask over TT timesteps (float4 loads, 16B aligned)
    for (int i = threadIdx.x; i < NIN; i += 512) {
        const float4* xr = (const float4*)(xb + (size_t)i * TSN);
        unsigned m = 0;
#pragma unroll
        for (int j4 = 0; j4 < TT / 4; ++j4) {
            float4 v = xr[j4];
            if (v.x != 0.0f) m |= 1u << (j4 * 4 + 0);
            if (v.y != 0.0f) m |= 1u << (j4 * 4 + 1);
            if (v.z != 0.0f) m |= 1u << (j4 * 4 + 2);
            if (v.w != 0.0f) m |= 1u << (j4 * 4 + 3);
        }
        msk[i] = m;
    }
    __syncthreads();

    // phase 2: build 20 per-t event lists in parallel (warp w -> t = w, w+16)
    {
        int wid  = threadIdx.x >> 5;
        int lane = threadIdx.x & 31;
        for (int t = wid; t < TT; t += 16) {
            int base = 0;
            for (int c = 0; c < NIN / 32; ++c) {
                int i = c * 32 + lane;
                bool a = (msk[i] >> t) & 1u;
                unsigned bal = __ballot_sync(0xffffffffu, a);
                if (a) {
                    int pos = base + __popc(bal & ((1u << lane) - 1u));
                    if (pos < TCAP - 12) tl[t][pos] = (unsigned short)i;
                }
                base += __popc(bal);
            }
            if (base > TCAP - 12) base = TCAP - 12;
            if (lane < 12) tl[t][base + lane] = (unsigned short)NIN;   // zero-row pads
            if (lane == 0) tcnt[t] = (base + 3) & ~3;
        }
    }
    __syncthreads();

    int o2 = threadIdx.x * 2;
    const float* wbase = g_w1t + o2;

#define LW(I) (*(const float2*)(wbase + (size_t)(I) * NHID))

    // two passes of 10 timesteps each (keeps accumulators at 20 regs)
#pragma unroll
    for (int p = 0; p < 2; ++p) {
        float2 A[10];
#pragma unroll
        for (int tt = 0; tt < 10; ++tt) {
            int t = p * 10 + tt;
            const unsigned short* lt = tl[t];
            int n = tcnt[t];
            float2 a = make_float2(0.f, 0.f);
            ushort4 I = *(const ushort4*)&lt[0];
            float2 w0 = LW(I.x), w1 = LW(I.y), w2 = LW(I.z), w3 = LW(I.w);
            for (int e = 0; e < n; e += 4) {
                ushort4 I2 = *(const ushort4*)&lt[e + 4];
                float2 p0 = LW(I2.x), p1 = LW(I2.y);
                a.x += w0.x; a.y += w0.y;
                a.x += w1.x; a.y += w1.y;
                float2 p2 = LW(I2.z), p3 = LW(I2.w);
                a.x += w2.x; a.y += w2.y;
                a.x += w3.x; a.y += w3.y;
                w0 = p0; w1 = p1; w2 = p2; w3 = p3;
            }
            A[tt] = a;
        }

        // staged coalesced writes: two halves of 512 outputs
#pragma unroll 1
        for (int h = 0; h < 2; ++h) {
            __syncthreads();
            if ((int)(threadIdx.x >> 8) == h) {
                int ol = (threadIdx.x & 255) * 2;
#pragma unroll
                for (int j = 0; j < 10; ++j) { wb[j][ol] = A[j].x; wb[j][ol + 1] = A[j].y; }
            }
            __syncthreads();
            int obase = b * NHID + h * 512;
            for (int idx = threadIdx.x; idx < 512 * 10; idx += 512) {
                int oo = idx / 10, j = idx - oo * 10;
                g_z1[(size_t)(obase + oo) * TSN + t0 + p * 10 + j] = wb[j][oo];
            }
        }
    }
#undef LW
}

// ---------------- t-parallel 77-tap causal FIR, u written in-place into g_z1 ----------------
#define WQ 146
__global__ __launch_bounds__(256) void conv1_kernel() {
    __shared__ float srm_s[KS];
    __shared__ float phys[2][4][WQ];

    int tid = threadIdx.x;
    int ty = tid >> 7;          // row within block
    int l  = tid & 127;

    for (int k = tid; k < KS; k += 256) srm_s[k] = g_srm[k];

    size_t row = (size_t)blockIdx.x * 2 + ty;
    float* zrow = g_z1 + row * TSN;

    // stage: win index wi in [-4, 576); win[76 + t] = z[t], zeros before
    for (int idx = l; idx < 580; idx += 128) {
        int wi = idx - 4;
        float v = 0.0f;
        if (wi >= 76 && wi < 576) v = zrow[wi - 76];
        phys[ty][idx & 3][idx >> 2] = v;
    }
    __syncthreads();

#define S(WI) phys[ty][((WI) + 4) & 3][((WI) + 4) >> 2]
    bool active = (l < 125);
    int tb = active ? l * 4 : 0;
    float u[4] = {0.f, 0.f, 0.f, 0.f};
    if (active) {
        float v[4];
        v[0] = S(tb + 76); v[1] = S(tb + 77); v[2] = S(tb + 78); v[3] = S(tb + 79);
#pragma unroll
        for (int k = 0; k < KS; ++k) {
            float w = srm_s[k];
            u[0] += w * v[0];
            u[1] += w * v[1];
            u[2] += w * v[2];
            u[3] += w * v[3];
            if (k + 1 < KS) {
                v[3] = v[2]; v[2] = v[1]; v[1] = v[0];
                v[0] = S(tb + 76 - k - 1);
            }
        }
    }
    __syncthreads();   // single, block-wide: all reads done before in-place overwrite
    if (active) {
        float4* uo = (float4*)(zrow + tb);
        *uo = make_float4(u[0], u[1], u[2], u[3]);
    }
#undef S
}

// ---------------- LIF scan (refractory feedback), one thread per row; u8 spike out ----------------
#define LIF_STEP(UIN, SOUT)                                             \
    {                                                                   \
        float u_ = (UIN) + rb[0];                                       \
        float s_ = (u_ >= THETA) ? 1.0f : 0.0f;                         \
        _Pragma("unroll")                                               \
        for (int j_ = 0; j_ < 9; ++j_) rb[j_] = rb[j_ + 1] + s_ * rk[j_ + 1]; \
        rb[9] = s_ * rk[10];                                            \
        (SOUT) = s_;                                                    \
    }

__global__ __launch_bounds__(256) void scan1_kernel() {
    float rk[KR];
#pragma unroll
    for (int j = 0; j < KR; ++j) rk[j] = g_refk[j];

    size_t r = (size_t)blockIdx.x * blockDim.x + threadIdx.x;   // 0..65535
    const float4* u  = (const float4*)(g_z1 + r * TSN);
    uchar4*      sp = (uchar4*)(g_s1 + r * TSN);

    float rb[10];
#pragma unroll
    for (int j = 0; j < 10; ++j) rb[j] = 0.0f;

    for (int c = 0; c < TSN / 4; ++c) {
        float4 uu = u[c];
        float s0, s1v, s2v, s3;
        LIF_STEP(uu.x, s0);
        LIF_STEP(uu.y, s1v);
        LIF_STEP(uu.z, s2v);
        LIF_STEP(uu.w, s3);
        uchar4 so;
        so.x = (unsigned char)s0;
        so.y = (unsigned char)s1v;
        so.z = (unsigned char)s2v;
        so.w = (unsigned char)s3;
        sp[c] = so;
    }
}

// ---------------- layer-2 GEMM: z2[b,o,t] = sum_i W2[o,i] * s1[b,i,t] (s1 is u8 0/1) ----------------
__global__ __launch_bounds__(320) void dense2_kernel(const float* __restrict__ w2) {
    __shared__ float ws[NOUT * NHID];
    int lt = threadIdx.y * 32 + threadIdx.x;
    for (int k = lt; k < NOUT * NHID; k += 320) ws[k] = w2[k];
    __syncthreads();

    int q = blockIdx.x * 32 + threadIdx.x;  // uchar4 index along t, 0..124
    if (q >= TSN / 4) return;
    int o = threadIdx.y;
    int b = blockIdx.y;

    const uchar4* s1b = ((const uchar4*)(g_s1 + (size_t)b * NHID * TSN)) + q;
    const float*  wr  = ws + o * NHID;

    float4 acc = make_float4(0.f, 0.f, 0.f, 0.f);
#pragma unroll 8
    for (int i = 0; i < NHID; ++i) {
        float w = wr[i];
        uchar4 s = s1b[(size_t)i * (TSN / 4)];
        acc.x += w * (float)s.x;
        acc.y += w * (float)s.y;
        acc.z += w * (float)s.z;
        acc.w += w * (float)s.w;
    }
    float4* zo = ((float4*)(g_z2 + ((size_t)(b * NOUT + o)) * TSN)) + q;
    *zo = acc;
}

// ---------------- layer-2 conv (t-parallel) ----------------
__global__ void conv2_kernel() {
    __shared__ float srm_s[KS];
    for (int k = threadIdx.x; k < KS; k += blockDim.x) srm_s[k] = g_srm[k];
    __syncthreads();

    int idx = blockIdx.x * blockDim.x + threadIdx.x;
    int nc = TSN / 4;
    int total = BB * NOUT * nc;
    if (idx >= total) return;
    int r = idx / nc, c = idx % nc;
    const float* z = g_z2 + (size_t)r * TSN;
    int tb = c * 4;
    float u0 = 0.f, u1 = 0.f, u2 = 0.f, u3 = 0.f;
    for (int k = 0; k < KS; ++k) {
        float w = srm_s[k];
        int t = tb - k;
        if (t + 3 >= 0) {
            if (t     >= 0) u0 += w * z[t];
            if (t + 1 >= 0) u1 += w * z[t + 1];
            if (t + 2 >= 0) u2 += w * z[t + 2];
            u3 += w * z[t + 3];
        }
    }
    float* uo = g_u2 + (size_t)r * TSN + tb;
    uo[0] = u0; uo[1] = u1; uo[2] = u2; uo[3] = u3;
}

// ---------------- layer-2 LIF scan -> final output ----------------
__global__ void scan2_kernel(float* __restrict__ out) {
    float rk[KR];
#pragma unroll
    for (int j = 0; j < KR; ++j) rk[j] = g_refk[j];

    int r = blockIdx.x * blockDim.x + threadIdx.x;
    if (r >= BB * NOUT) return;
    const float* u = g_u2 + (size_t)r * TSN;
    float* o = out + (size_t)r * TSN;

    float rb[10];
#pragma unroll
    for (int j = 0; j < 10; ++j) rb[j] = 0.0f;

    for (int t = 0; t < TSN; ++t) {
        float s;
        LIF_STEP(u[t], s);
        o[t] = s;
    }
}

// ---------------- launcher ----------------
extern "C" void kernel_launch(void* const* d_in, const int* in_sizes, int n_in,
                              void* d_out, int out_size) {
    const float* x  = (const float*)d_in[0];   // spike_input [64,1024,500]
    const float* w1 = (const float*)d_in[1];   // W1 [1024,1024]
    const float* w2 = (const float*)d_in[2];   // W2 [10,1024]
    float* out = (float*)d_out;                // s2 [64,10,500]

    init_kernel<<<1, 128>>>();                              // launch 1
    transpose_kernel<<<dim3(32, 32), dim3(32, 8)>>>(w1);    // launch 2
    dummy_kernel<<<1, 32>>>();                              // launch 3 (profiler shim)
    spmm1_kernel<<<dim3(NTG, BB), 512>>>(x);                // launch 4 <- ncu capture
    conv1_kernel<<<BB * NHID / 2, 256>>>();                 // launch 5
    scan1_kernel<<<BB * NHID / 256, 256>>>();               // launch 6
    dense2_kernel<<<dim3(4, BB), dim3(32, 10)>>>(w2);       // launch 7
    conv2_kernel<<<(BB * NOUT * (TSN / 4) + 255) / 256, 256>>>();  // launch 8
    scan2_kernel<<<(BB * NOUT + 255) / 256, 256>>>(out);    // launch 9
}

// round 9
// speedup vs baseline: 3.2740x; 1.1019x over previous
#include <cuda_runtime.h>
#include <math.h>

// ---------------- problem constants ----------------
#define BB    64
#define NIN   1024
#define NHID  1024
#define NOUT  10
#define TSN   500          // time bins
#define KS    77           // SRM kernel taps (truncated alpha kernel, tau=10)
#define KR    11           // refractory kernel taps (tau=1), REF[0]==0
#define THETA 10.0f
#define TT    20           // timesteps per spmm block
#define NTG   (TSN / TT)   // 25
#define TCAP  384          // per-t event list capacity (mean 51, sigma 7)

// ---------------- scratch (static device memory; no allocations) ----------------
__device__ float g_srm[KS];
__device__ float g_refk[KR];
__device__ float g_w1t[(size_t)(NIN + 1) * NHID];        // W1^T [i][o]; row NIN is all-zero (pad row)
__device__ float g_z1[(size_t)BB * NHID * TSN];          // 131 MB (z, then u in-place)
__device__ unsigned char g_s1[(size_t)BB * NHID * TSN];  // 33 MB (binary spikes as u8)
__device__ float g_z2[(size_t)BB * NOUT * TSN];          // 1.28 MB
__device__ float g_u2[(size_t)BB * NOUT * TSN];          // 1.28 MB
__device__ float g_dummy[32];

// ---------------- kernel tap init (double, matches python math.exp -> f32) ----------------
__global__ void init_kernel() {
    int i = threadIdx.x;
    if (i < KS) {
        double t = (double)i;
        g_srm[i] = (float)(t / 10.0 * exp(1.0 - t / 10.0));
    }
    if (i < KR) {
        double t = (double)i;
        g_refk[i] = (float)(-20.0 * t * exp(1.0 - t));   // mult = -2*theta, tau_ref = 1
    }
    // zero pad row of W1^T (used by event-list padding)
    for (int k = threadIdx.x; k < NHID; k += blockDim.x)
        g_w1t[(size_t)NIN * NHID + k] = 0.0f;
}

// ---------------- W1 transpose: g_w1t[i][o] = W1[o][i] ----------------
__global__ void transpose_kernel(const float* __restrict__ w1) {
    __shared__ float tile[32][33];
    int i0 = blockIdx.x * 32;
    int o0 = blockIdx.y * 32;
    for (int j = threadIdx.y; j < 32; j += 8)
        tile[j][threadIdx.x] = w1[(size_t)(o0 + j) * NIN + i0 + threadIdx.x];
    __syncthreads();
    for (int j = threadIdx.y; j < 32; j += 8)
        g_w1t[(size_t)(i0 + j) * NHID + o0 + threadIdx.x] = tile[threadIdx.x][j];
}

// ---------------- dummy (shifts launch index so ncu's capture lands on spmm1) ----------------
__global__ void dummy_kernel() {
    if (threadIdx.x < 32) g_dummy[threadIdx.x] = (float)threadIdx.x;
}

// ---------------- layer-1 GEMM via per-timestep event lists ----------------
// block = (b, t-group of TT=20); 512 threads, each owns 2 output rows (o2, o2+1).
// For each t: z1[b,o,t0+t] = sum over active i ASCENDING of W1[o,i]  (order-exact).
// Branchless inner loop: ushort4 index fetch -> 4 x LDG.64 -> 8 FADD, 4-deep prefetch.
// Lists padded with index NIN (all-zero W row): +0.0f adds are exact no-ops.
// 3 blocks/SM: cold A[] spills cost one fill each at the staging write.
__global__ __launch_bounds__(512, 3) void spmm1_kernel(const float* __restrict__ x) {
    __shared__ unsigned msk[NIN];
    __shared__ unsigned short tl[TT][TCAP];
    __shared__ int tcnt[TT];
    __shared__ float wb[10][513];

    int b  = blockIdx.y;
    int t0 = blockIdx.x * TT;
    const float* xb = x + (size_t)b * NIN * TSN + t0;

    // phase 1: per-input activity bitmask over TT timesteps (float4 loads, 16B aligned)
    for (int i = threadIdx.x; i < NIN; i += 512) {
        const float4* xr = (const float4*)(xb + (size_t)i * TSN);
        unsigned m = 0;
#pragma unroll
        for (int j4 = 0; j4 < TT / 4; ++j4) {
            float4 v = xr[j4];
            if (v.x != 0.0f) m |= 1u << (j4 * 4 + 0);
            if (v.y != 0.0f) m |= 1u << (j4 * 4 + 1);
            if (v.z != 0.0f) m |= 1u << (j4 * 4 + 2);
            if (v.w != 0.0f) m |= 1u << (j4 * 4 + 3);
        }
        msk[i] = m;
    }
    __syncthreads();

    // phase 2: build 20 per-t event lists in parallel (warp w -> t = w, w+16)
    {
        int wid  = threadIdx.x >> 5;
        int lane = threadIdx.x & 31;
        for (int t = wid; t < TT; t += 16) {
            int base = 0;
            for (int c = 0; c < NIN / 32; ++c) {
                int i = c * 32 + lane;
                bool a = (msk[i] >> t) & 1u;
                unsigned bal = __ballot_sync(0xffffffffu, a);
                if (a) {
                    int pos = base + __popc(bal & ((1u << lane) - 1u));
                    if (pos < TCAP - 12) tl[t][pos] = (unsigned short)i;
                }
                base += __popc(bal);
            }
            if (base > TCAP - 12) base = TCAP - 12;
            if (lane < 12) tl[t][base + lane] = (unsigned short)NIN;   // zero-row pads
            if (lane == 0) tcnt[t] = (base + 3) & ~3;
        }
    }
    __syncthreads();

    int o2 = threadIdx.x * 2;
    const float* wbase = g_w1t + o2;

#define LW(I) (*(const float2*)(wbase + (size_t)(I) * NHID))

    // two passes of 10 timesteps each (keeps hot accumulator a small)
#pragma unroll
    for (int p = 0; p < 2; ++p) {
        float2 A[10];
#pragma unroll
        for (int tt = 0; tt < 10; ++tt) {
            int t = p * 10 + tt;
            const unsigned short* lt = tl[t];
            int n = tcnt[t];
            float2 a = make_float2(0.f, 0.f);
            ushort4 I = *(const ushort4*)&lt[0];
            float2 w0 = LW(I.x), w1 = LW(I.y), w2 = LW(I.z), w3 = LW(I.w);
            for (int e = 0; e < n; e += 4) {
                ushort4 I2 = *(const ushort4*)&lt[e + 4];
                float2 p0 = LW(I2.x), p1 = LW(I2.y);
                a.x += w0.x; a.y += w0.y;
                a.x += w1.x; a.y += w1.y;
                float2 p2 = LW(I2.z), p3 = LW(I2.w);
                a.x += w2.x; a.y += w2.y;
                a.x += w3.x; a.y += w3.y;
                w0 = p0; w1 = p1; w2 = p2; w3 = p3;
            }
            A[tt] = a;
        }

        // staged coalesced writes: two halves of 512 outputs
#pragma unroll 1
        for (int h = 0; h < 2; ++h) {
            __syncthreads();
            if ((int)(threadIdx.x >> 8) == h) {
                int ol = (threadIdx.x & 255) * 2;
#pragma unroll
                for (int j = 0; j < 10; ++j) { wb[j][ol] = A[j].x; wb[j][ol + 1] = A[j].y; }
            }
            __syncthreads();
            int obase = b * NHID + h * 512;
            for (int idx = threadIdx.x; idx < 512 * 10; idx += 512) {
                int oo = idx / 10, j = idx - oo * 10;
                g_z1[(size_t)(obase + oo) * TSN + t0 + p * 10 + j] = wb[j][oo];
            }
        }
    }
#undef LW
}

// ---------------- t-parallel 77-tap causal FIR, u written in-place into g_z1 ----------------
// 4 rows/block, 64 threads/row, 8 outputs/thread: per tap 1 LDS + 8 FFMA.
// smem deinterleaved by 8 (phys[r][wi&7][wi>>3]) so the stride-8 window reads are
// conflict-free (a warp's 32 lanes share wi&7 and span consecutive wi>>3).
#define NR  4
#define WQ8 74
__global__ __launch_bounds__(256) void conv1_kernel() {
    __shared__ float srm_s[KS];
    __shared__ float phys[NR][8][WQ8];

    int tid = threadIdx.x;
    int r = tid >> 6;           // row within block, 0..3
    int l = tid & 63;           // 0..63

    for (int k = tid; k < KS; k += 256) srm_s[k] = g_srm[k];

    size_t row = (size_t)blockIdx.x * NR + r;
    float* zrow = g_z1 + row * TSN;

    // stage window: win[wi] = z[wi-76] for wi in [76,576), else 0; wi in [0,584)
    for (int wi = l; wi < 584; wi += 64) {
        float v = (wi >= 76 && wi < 576) ? zrow[wi - 76] : 0.0f;
        phys[r][wi & 7][wi >> 3] = v;
    }
    __syncthreads();

#define S(WI) phys[r][(WI) & 7][(WI) >> 3]
    bool active = (l < 63);
    int tb = active ? l * 8 : 0;      // output base t, 0..496
    float u[8] = {0.f, 0.f, 0.f, 0.f, 0.f, 0.f, 0.f, 0.f};
    if (active) {
        float v[8];
#pragma unroll
        for (int j = 0; j < 8; ++j) v[j] = S(tb + 76 + j);
#pragma unroll
        for (int k = 0; k < KS; ++k) {
            float w = srm_s[k];
#pragma unroll
            for (int j = 0; j < 8; ++j) u[j] += w * v[j];
            if (k + 1 < KS) {
#pragma unroll
                for (int j = 7; j > 0; --j) v[j] = v[j - 1];
                v[0] = S(tb + 75 - k);
            }
        }
    }
    __syncthreads();   // single, block-wide: all reads done before in-place overwrite
    if (active) {
        *(float4*)(zrow + tb)     = make_float4(u[0], u[1], u[2], u[3]);
        if (tb + 7 < TSN)
            *(float4*)(zrow + tb + 4) = make_float4(u[4], u[5], u[6], u[7]);
    }
#undef S
}

// ---------------- LIF scan (refractory feedback), one thread per row; u8 spike out ----------------
#define LIF_STEP(UIN, SOUT)                                             \
    {                                                                   \
        float u_ = (UIN) + rb[0];                                       \
        float s_ = (u_ >= THETA) ? 1.0f : 0.0f;                         \
        _Pragma("unroll")                                               \
        for (int j_ = 0; j_ < 9; ++j_) rb[j_] = rb[j_ + 1] + s_ * rk[j_ + 1]; \
        rb[9] = s_ * rk[10];                                            \
        (SOUT) = s_;                                                    \
    }

__global__ __launch_bounds__(256) void scan1_kernel() {
    float rk[KR];
#pragma unroll
    for (int j = 0; j < KR; ++j) rk[j] = g_refk[j];

    size_t r = (size_t)blockIdx.x * blockDim.x + threadIdx.x;   // 0..65535
    const float4* u  = (const float4*)(g_z1 + r * TSN);
    uchar4*      sp = (uchar4*)(g_s1 + r * TSN);

    float rb[10];
#pragma unroll
    for (int j = 0; j < 10; ++j) rb[j] = 0.0f;

    for (int c = 0; c < TSN / 4; ++c) {
        float4 uu = u[c];
        float s0, s1v, s2v, s3;
        LIF_STEP(uu.x, s0);
        LIF_STEP(uu.y, s1v);
        LIF_STEP(uu.z, s2v);
        LIF_STEP(uu.w, s3);
        uchar4 so;
        so.x = (unsigned char)s0;
        so.y = (unsigned char)s1v;
        so.z = (unsigned char)s2v;
        so.w = (unsigned char)s3;
        sp[c] = so;
    }
}

// ---------------- layer-2 GEMM: z2[b,o,t] = sum_i W2[o,i] * s1[b,i,t] (s1 is u8 0/1) ----------------
__global__ __launch_bounds__(320) void dense2_kernel(const float* __restrict__ w2) {
    __shared__ float ws[NOUT * NHID];
    int lt = threadIdx.y * 32 + threadIdx.x;
    for (int k = lt; k < NOUT * NHID; k += 320) ws[k] = w2[k];
    __syncthreads();

    int q = blockIdx.x * 32 + threadIdx.x;  // uchar4 index along t, 0..124
    if (q >= TSN / 4) return;
    int o = threadIdx.y;
    int b = blockIdx.y;

    const uchar4* s1b = ((const uchar4*)(g_s1 + (size_t)b * NHID * TSN)) + q;
    const float*  wr  = ws + o * NHID;

    float4 acc = make_float4(0.f, 0.f, 0.f, 0.f);
#pragma unroll 8
    for (int i = 0; i < NHID; ++i) {
        float w = wr[i];
        uchar4 s = s1b[(size_t)i * (TSN / 4)];
        acc.x += w * (float)s.x;
        acc.y += w * (float)s.y;
        acc.z += w * (float)s.z;
        acc.w += w * (float)s.w;
    }
    float4* zo = ((float4*)(g_z2 + ((size_t)(b * NOUT + o)) * TSN)) + q;
    *zo = acc;
}

// ---------------- layer-2 conv (t-parallel) ----------------
__global__ void conv2_kernel() {
    __shared__ float srm_s[KS];
    for (int k = threadIdx.x; k < KS; k += blockDim.x) srm_s[k] = g_srm[k];
    __syncthreads();

    int idx = blockIdx.x * blockDim.x + threadIdx.x;
    int nc = TSN / 4;
    int total = BB * NOUT * nc;
    if (idx >= total) return;
    int r = idx / nc, c = idx % nc;
    const float* z = g_z2 + (size_t)r * TSN;
    int tb = c * 4;
    float u0 = 0.f, u1 = 0.f, u2 = 0.f, u3 = 0.f;
    for (int k = 0; k < KS; ++k) {
        float w = srm_s[k];
        int t = tb - k;
        if (t + 3 >= 0) {
            if (t     >= 0) u0 += w * z[t];
            if (t + 1 >= 0) u1 += w * z[t + 1];
            if (t + 2 >= 0) u2 += w * z[t + 2];
            u3 += w * z[t + 3];
        }
    }
    float* uo = g_u2 + (size_t)r * TSN + tb;
    uo[0] = u0; uo[1] = u1; uo[2] = u2; uo[3] = u3;
}

// ---------------- layer-2 LIF scan -> final output (vectorized loads) ----------------
__global__ void scan2_kernel(float* __restrict__ out) {
    float rk[KR];
#pragma unroll
    for (int j = 0; j < KR; ++j) rk[j] = g_refk[j];

    int r = blockIdx.x * blockDim.x + threadIdx.x;
    if (r >= BB * NOUT) return;
    const float4* u = (const float4*)(g_u2 + (size_t)r * TSN);
    float4* o = (float4*)(out + (size_t)r * TSN);

    float rb[10];
#pragma unroll
    for (int j = 0; j < 10; ++j) rb[j] = 0.0f;

    for (int c = 0; c < TSN / 4; ++c) {
        float4 uu = u[c];
        float4 so;
        LIF_STEP(uu.x, so.x);
        LIF_STEP(uu.y, so.y);
        LIF_STEP(uu.z, so.z);
        LIF_STEP(uu.w, so.w);
        o[c] = so;
    }
}

// ---------------- launcher ----------------
extern "C" void kernel_launch(void* const* d_in, const int* in_sizes, int n_in,
                              void* d_out, int out_size) {
    const float* x  = (const float*)d_in[0];   // spike_input [64,1024,500]
    const float* w1 = (const float*)d_in[1];   // W1 [1024,1024]
    const float* w2 = (const float*)d_in[2];   // W2 [10,1024]
    float* out = (float*)d_out;                // s2 [64,10,500]

    init_kernel<<<1, 128>>>();                              // launch 1
    transpose_kernel<<<dim3(32, 32), dim3(32, 8)>>>(w1);    // launch 2
    dummy_kernel<<<1, 32>>>();                              // launch 3 (profiler shim)
    spmm1_kernel<<<dim3(NTG, BB), 512>>>(x);                // launch 4 <- ncu capture
    conv1_kernel<<<BB * NHID / NR, 256>>>();                // launch 5
    scan1_kernel<<<BB * NHID / 256, 256>>>();               // launch 6
    dense2_kernel<<<dim3(4, BB), dim3(32, 10)>>>(w2);       // launch 7
    conv2_kernel<<<(BB * NOUT * (TSN / 4) + 255) / 256, 256>>>();  // launch 8
    scan2_kernel<<<(BB * NOUT + 255) / 256, 256>>>(out);    // launch 9
}

// round 12
// speedup vs baseline: 3.3357x; 1.0189x over previous
#include <cuda_runtime.h>
#include <math.h>

// ---------------- problem constants ----------------
#define BB    64
#define NIN   1024
#define NHID  1024
#define NOUT  10
#define TSN   500          // time bins
#define KS    77           // SRM kernel taps (truncated alpha kernel, tau=10)
#define KR    11           // refractory kernel taps (tau=1), REF[0]==0
#define THETA 10.0f
#define TT    20           // timesteps per spmm block
#define NTG   (TSN / TT)   // 25
#define TCAP  384          // per-t event list capacity (mean 51, sigma 7)

// ---------------- scratch (static device memory; no allocations) ----------------
__device__ float g_srm[KS];
__device__ float g_refk[KR];
__device__ float g_w1t[(size_t)(NIN + 1) * NHID];        // W1^T [i][o]; row NIN is all-zero (pad row)
__device__ float g_z1[(size_t)BB * NHID * TSN];          // 131 MB (z, then u in-place)
__device__ unsigned char g_s1[(size_t)BB * NHID * TSN];  // 33 MB (binary spikes as u8)
__device__ float g_z2[(size_t)BB * NOUT * TSN];          // 1.28 MB (z2, then u2 in-place)

// ---------------- kernel tap init (double, matches python math.exp -> f32) ----------------
__global__ void init_kernel() {
    int i = threadIdx.x;
    if (i < KS) {
        double t = (double)i;
        g_srm[i] = (float)(t / 10.0 * exp(1.0 - t / 10.0));
    }
    if (i < KR) {
        double t = (double)i;
        g_refk[i] = (float)(-20.0 * t * exp(1.0 - t));   // mult = -2*theta, tau_ref = 1
    }
    // zero pad row of W1^T (used by event-list padding)
    for (int k = threadIdx.x; k < NHID; k += blockDim.x)
        g_w1t[(size_t)NIN * NHID + k] = 0.0f;
}

// ---------------- W1 transpose: g_w1t[i][o] = W1[o][i] ----------------
__global__ void transpose_kernel(const float* __restrict__ w1) {
    __shared__ float tile[32][33];
    int i0 = blockIdx.x * 32;
    int o0 = blockIdx.y * 32;
    for (int j = threadIdx.y; j < 32; j += 8)
        tile[j][threadIdx.x] = w1[(size_t)(o0 + j) * NIN + i0 + threadIdx.x];
    __syncthreads();
    for (int j = threadIdx.y; j < 32; j += 8)
        g_w1t[(size_t)(i0 + j) * NHID + o0 + threadIdx.x] = tile[threadIdx.x][j];
}

// ---------------- layer-1 GEMM via per-timestep event lists ----------------
// block = (b, t-group of TT=20); 512 threads, each owns 2 output rows (o2, o2+1).
// For each t: z1[b,o,t0+t] = sum over active i ASCENDING of W1[o,i]  (order-exact).
// Branchless inner loop: ushort4 index fetch -> 4 x LDG.64 -> 8 FADD, 4-deep prefetch.
// Lists padded with index NIN (all-zero W row): +0.0f adds are exact no-ops.
__global__ __launch_bounds__(512, 3) void spmm1_kernel(const float* __restrict__ x) {
    __shared__ unsigned msk[NIN];
    __shared__ unsigned short tl[TT][TCAP];
    __shared__ int tcnt[TT];
    __shared__ float wb[10][513];

    int b  = blockIdx.y;
    int t0 = blockIdx.x * TT;
    const float* xb = x + (size_t)b * NIN * TSN + t0;

    // phase 1: per-input activity bitmask over TT timesteps (float4 loads, 16B aligned)
    for (int i = threadIdx.x; i < NIN; i += 512) {
        const float4* xr = (const float4*)(xb + (size_t)i * TSN);
        unsigned m = 0;
#pragma unroll
        for (int j4 = 0; j4 < TT / 4; ++j4) {
            float4 v = xr[j4];
            if (v.x != 0.0f) m |= 1u << (j4 * 4 + 0);
            if (v.y != 0.0f) m |= 1u << (j4 * 4 + 1);
            if (v.z != 0.0f) m |= 1u << (j4 * 4 + 2);
            if (v.w != 0.0f) m |= 1u << (j4 * 4 + 3);
        }
        msk[i] = m;
    }
    __syncthreads();

    // phase 2: build 20 per-t event lists in parallel (warp w -> t = w, w+16)
    {
        int wid  = threadIdx.x >> 5;
        int lane = threadIdx.x & 31;
        for (int t = wid; t < TT; t += 16) {
            int base = 0;
            for (int c = 0; c < NIN / 32; ++c) {
                int i = c * 32 + lane;
                bool a = (msk[i] >> t) & 1u;
                unsigned bal = __ballot_sync(0xffffffffu, a);
                if (a) {
                    int pos = base + __popc(bal & ((1u << lane) - 1u));
                    if (pos < TCAP - 12) tl[t][pos] = (unsigned short)i;
                }
                base += __popc(bal);
            }
            if (base > TCAP - 12) base = TCAP - 12;
            if (lane < 12) tl[t][base + lane] = (unsigned short)NIN;   // zero-row pads
            if (lane == 0) tcnt[t] = (base + 3) & ~3;
        }
    }
    __syncthreads();

    int o2 = threadIdx.x * 2;
    const float* wbase = g_w1t + o2;

#define LW(I) (*(const float2*)(wbase + (size_t)(I) * NHID))

    // two passes of 10 timesteps each (keeps hot accumulator a small)
#pragma unroll
    for (int p = 0; p < 2; ++p) {
        float2 A[10];
#pragma unroll
        for (int tt = 0; tt < 10; ++tt) {
            int t = p * 10 + tt;
            const unsigned short* lt = tl[t];
            int n = tcnt[t];
            float2 a = make_float2(0.f, 0.f);
            ushort4 I = *(const ushort4*)&lt[0];
            float2 w0 = LW(I.x), w1 = LW(I.y), w2 = LW(I.z), w3 = LW(I.w);
            for (int e = 0; e < n; e += 4) {
                ushort4 I2 = *(const ushort4*)&lt[e + 4];
                float2 p0 = LW(I2.x), p1 = LW(I2.y);
                a.x += w0.x; a.y += w0.y;
                a.x += w1.x; a.y += w1.y;
                float2 p2 = LW(I2.z), p3 = LW(I2.w);
                a.x += w2.x; a.y += w2.y;
                a.x += w3.x; a.y += w3.y;
                w0 = p0; w1 = p1; w2 = p2; w3 = p3;
            }
            A[tt] = a;
        }

        // staged coalesced writes: two halves of 512 outputs
#pragma unroll 1
        for (int h = 0; h < 2; ++h) {
            __syncthreads();
            if ((int)(threadIdx.x >> 8) == h) {
                int ol = (threadIdx.x & 255) * 2;
#pragma unroll
                for (int j = 0; j < 10; ++j) { wb[j][ol] = A[j].x; wb[j][ol + 1] = A[j].y; }
            }
            __syncthreads();
            int obase = b * NHID + h * 512;
            for (int idx = threadIdx.x; idx < 512 * 10; idx += 512) {
                int oo = idx / 10, j = idx - oo * 10;
                g_z1[(size_t)(obase + oo) * TSN + t0 + p * 10 + j] = wb[j][oo];
            }
        }
    }
#undef LW
}

// ---------------- generic t-parallel 77-tap causal FIR, u written in-place ----------------
// 4 rows/block, 64 threads/row, 8 outputs/thread: per tap 1 LDS + 8 FFMA.
// smem deinterleaved by 8 (phys[r][wi&7][wi>>3]) so the stride-8 window reads are
// conflict-free. Used for layer-1 (g_z1, 65536 rows) AND layer-2 (g_z2, 640 rows).
#define NR  4
#define WQ8 74
__global__ __launch_bounds__(256) void conv_kernel(float* __restrict__ buf) {
    __shared__ float srm_s[KS];
    __shared__ float phys[NR][8][WQ8];

    int tid = threadIdx.x;
    int r = tid >> 6;           // row within block, 0..3
    int l = tid & 63;           // 0..63

    for (int k = tid; k < KS; k += 256) srm_s[k] = g_srm[k];

    size_t row = (size_t)blockIdx.x * NR + r;
    float* zrow = buf + row * TSN;

    // stage window: win[wi] = z[wi-76] for wi in [76,576), else 0; wi in [0,584)
    for (int wi = l; wi < 584; wi += 64) {
        float v = (wi >= 76 && wi < 576) ? zrow[wi - 76] : 0.0f;
        phys[r][wi & 7][wi >> 3] = v;
    }
    __syncthreads();

#define S(WI) phys[r][(WI) & 7][(WI) >> 3]
    bool active = (l < 63);
    int tb = active ? l * 8 : 0;      // output base t, 0..496
    float u[8] = {0.f, 0.f, 0.f, 0.f, 0.f, 0.f, 0.f, 0.f};
    if (active) {
        float v[8];
#pragma unroll
        for (int j = 0; j < 8; ++j) v[j] = S(tb + 76 + j);
#pragma unroll
        for (int k = 0; k < KS; ++k) {
            float w = srm_s[k];
#pragma unroll
            for (int j = 0; j < 8; ++j) u[j] += w * v[j];
            if (k + 1 < KS) {
#pragma unroll
                for (int j = 7; j > 0; --j) v[j] = v[j - 1];
                v[0] = S(tb + 75 - k);
            }
        }
    }
    __syncthreads();   // single, block-wide: all reads done before in-place overwrite
    if (active) {
        *(float4*)(zrow + tb)     = make_float4(u[0], u[1], u[2], u[3]);
        if (tb + 7 < TSN)
            *(float4*)(zrow + tb + 4) = make_float4(u[4], u[5], u[6], u[7]);
    }
#undef S
}

// ---------------- LIF scan (refractory feedback), one thread per row; u8 spike out ----------------
#define LIF_STEP(UIN, SOUT)                                             \
    {                                                                   \
        float u_ = (UIN) + rb[0];                                       \
        float s_ = (u_ >= THETA) ? 1.0f : 0.0f;                         \
        _Pragma("unroll")                                               \
        for (int j_ = 0; j_ < 9; ++j_) rb[j_] = rb[j_ + 1] + s_ * rk[j_ + 1]; \
        rb[9] = s_ * rk[10];                                            \
        (SOUT) = s_;                                                    \
    }

__global__ __launch_bounds__(256) void scan1_kernel() {
    float rk[KR];
#pragma unroll
    for (int j = 0; j < KR; ++j) rk[j] = g_refk[j];

    size_t r = (size_t)blockIdx.x * blockDim.x + threadIdx.x;   // 0..65535
    const float4* u  = (const float4*)(g_z1 + r * TSN);
    uchar4*      sp = (uchar4*)(g_s1 + r * TSN);

    float rb[10];
#pragma unroll
    for (int j = 0; j < 10; ++j) rb[j] = 0.0f;

    for (int c = 0; c < TSN / 4; ++c) {
        float4 uu = u[c];
        float s0, s1v, s2v, s3;
        LIF_STEP(uu.x, s0);
        LIF_STEP(uu.y, s1v);
        LIF_STEP(uu.z, s2v);
        LIF_STEP(uu.w, s3);
        uchar4 so;
        so.x = (unsigned char)s0;
        so.y = (unsigned char)s1v;
        so.z = (unsigned char)s2v;
        so.w = (unsigned char)s3;
        sp[c] = so;
    }
}

// ---------------- layer-2 GEMM: z2[b,o,t] = sum_i W2[o,i] * s1[b,i,t] (s1 is u8 0/1) ----------------
__global__ __launch_bounds__(320) void dense2_kernel(const float* __restrict__ w2) {
    __shared__ float ws[NOUT * NHID];
    int lt = threadIdx.y * 32 + threadIdx.x;
    for (int k = lt; k < NOUT * NHID; k += 320) ws[k] = w2[k];
    __syncthreads();

    int q = blockIdx.x * 32 + threadIdx.x;  // uchar4 index along t, 0..124
    if (q >= TSN / 4) return;
    int o = threadIdx.y;
    int b = blockIdx.y;

    const uchar4* s1b = ((const uchar4*)(g_s1 + (size_t)b * NHID * TSN)) + q;
    const float*  wr  = ws + o * NHID;

    float4 acc = make_float4(0.f, 0.f, 0.f, 0.f);
#pragma unroll 8
    for (int i = 0; i < NHID; ++i) {
        float w = wr[i];
        uchar4 s = s1b[(size_t)i * (TSN / 4)];
        acc.x += w * (float)s.x;
        acc.y += w * (float)s.y;
        acc.z += w * (float)s.z;
        acc.w += w * (float)s.w;
    }
    float4* zo = ((float4*)(g_z2 + ((size_t)(b * NOUT + o)) * TSN)) + q;
    *zo = acc;
}

// ---------------- layer-2 LIF scan -> final output (reads u in-place from g_z2) ----------------
__global__ void scan2_kernel(float* __restrict__ out) {
    float rk[KR];
#pragma unroll
    for (int j = 0; j < KR; ++j) rk[j] = g_refk[j];

    int r = blockIdx.x * blockDim.x + threadIdx.x;
    if (r >= BB * NOUT) return;
    const float4* u = (const float4*)(g_z2 + (size_t)r * TSN);
    float4* o = (float4*)(out + (size_t)r * TSN);

    float rb[10];
#pragma unroll
    for (int j = 0; j < 10; ++j) rb[j] = 0.0f;

    for (int c = 0; c < TSN / 4; ++c) {
        float4 uu = u[c];
        float4 so;
        LIF_STEP(uu.x, so.x);
        LIF_STEP(uu.y, so.y);
        LIF_STEP(uu.z, so.z);
        LIF_STEP(uu.w, so.w);
        o[c] = so;
    }
}

// ---------------- launcher ----------------
extern "C" void kernel_launch(void* const* d_in, const int* in_sizes, int n_in,
                              void* d_out, int out_size) {
    const float* x  = (const float*)d_in[0];   // spike_input [64,1024,500]
    const float* w1 = (const float*)d_in[1];   // W1 [1024,1024]
    const float* w2 = (const float*)d_in[2];   // W2 [10,1024]
    float* out = (float*)d_out;                // s2 [64,10,500]

    float* z1p; cudaGetSymbolAddress((void**)&z1p, g_z1);
    float* z2p; cudaGetSymbolAddress((void**)&z2p, g_z2);

    init_kernel<<<1, 128>>>();                              // launch 1
    transpose_kernel<<<dim3(32, 32), dim3(32, 8)>>>(w1);    // launch 2
    spmm1_kernel<<<dim3(NTG, BB), 512>>>(x);                // launch 3
    conv_kernel<<<BB * NHID / NR, 256>>>(z1p);              // launch 4 <- ncu capture
    scan1_kernel<<<BB * NHID / 256, 256>>>();               // launch 5
    dense2_kernel<<<dim3(4, BB), dim3(32, 10)>>>(w2);       // launch 6
    conv_kernel<<<BB * NOUT / NR, 256>>>(z2p);              // launch 7
    scan2_kernel<<<(BB * NOUT + 255) / 256, 256>>>(out);    // launch 8
}